// round 7
// baseline (speedup 1.0000x reference)
#include <cuda_runtime.h>

// N=8192 rows, C=5000 classes, RATIO=3
#define NC    5000
#define NT    512
#define NW    16
#define NV    3      // ceil(1250 float4 / 512 threads)
#define NV4   1250   // float4 count per row
#define HW    2048   // histogram words: 4096 bins, two 16-bit counts per word
#define CAP   1024   // threshold-bin candidate capacity (expected ~50-120)

__device__ double   g_loss = 0.0;
__device__ double   g_tsum = 0.0;
__device__ unsigned g_done = 0;

// order-preserving float->uint key (larger float <-> larger key)
__device__ __forceinline__ unsigned fkey(float f) {
    unsigned b = __float_as_uint(f);
    return (b & 0x80000000u) ? ~b : (b | 0x80000000u);
}
__device__ __forceinline__ float kinv(unsigned k) {
    return __uint_as_float((k & 0x80000000u) ? (k & 0x7FFFFFFFu) : ~k);
}
// fast softplus (MUFU-based)
__device__ __forceinline__ float sp(float x) {
    float l = __logf(1.f + __expf(-fabsf(x)));
    return x > 0.f ? x + l : l;
}

__global__ void __launch_bounds__(NT, 3)
hardneg(const float* __restrict__ pred, const float* __restrict__ target,
        float* __restrict__ out)
{
    __shared__ unsigned s_hist[HW];    // 8192 B : packed 16-bit counts (4096 bins)
    __shared__ unsigned s_cand[CAP];   // 4096 B
    __shared__ unsigned s_wsum[NW];
    __shared__ int      s_posr[NW];
    __shared__ float    s_accr[NW];
    __shared__ unsigned s_binv, s_kkv, s_tkey, s_krem;
    __shared__ int      s_cnt;

    const int tid  = threadIdx.x;
    const int lane = tid & 31;
    const int wid  = tid >> 5;
    const int row  = blockIdx.x;

    const float4* p4 = (const float4*)(pred   + (size_t)row * NC);
    const float4* t4 = (const float4*)(target + (size_t)row * NC);

    // zero histogram: 512 words of uint4 = one per thread
    ((uint4*)s_hist)[tid] = make_uint4(0, 0, 0, 0);
    if (tid == 0) s_cnt = 0;
    __syncthreads();

    // ---- pass A: load, classify, key (REGISTERS), histogram, positive BCE ----
    int   poscnt = 0;
    float accP   = 0.f;
    uint4 kreg[NV];

    #define PROC(px, tx, kout)                                             \
        do {                                                               \
            float _x = (px);                                               \
            if ((tx) != 0.f) {                                             \
                poscnt++; accP += sp(_x) - _x; (kout) = 0u;                \
            } else {                                                       \
                unsigned _k = fkey(_x); (kout) = _k;                       \
                atomicAdd(&s_hist[_k >> 21],                               \
                          ((_k >> 20) & 1u) ? 65536u : 1u);                \
            }                                                              \
        } while (0)

    #pragma unroll
    for (int j = 0; j < NV; j++) {
        int i = j * NT + tid;
        uint4 k = make_uint4(0, 0, 0, 0);
        if (j < NV - 1 || i < NV4) {
            float4 p = p4[i];
            float4 t = t4[i];
            PROC(p.x, t.x, k.x);
            PROC(p.y, t.y, k.y);
            PROC(p.z, t.z, k.z);
            PROC(p.w, t.w, k.w);
        }
        kreg[j] = k;
    }
    #undef PROC
    __syncthreads();

    // ---- locate threshold bin: suffix counts via shuffle scan ----
    // thread t owns bins [t*8, t*8+8) = words [t*4, t*4+4)
    unsigned w4[4];
    unsigned S = 0;
    #pragma unroll
    for (int j = 0; j < 4; j++) {
        unsigned v = s_hist[tid * 4 + j];
        w4[j] = v;
        S += (v & 0xFFFFu) + (v >> 16);
    }
    unsigned v = S;  // inclusive suffix within warp
    #pragma unroll
    for (int off = 1; off < 32; off <<= 1) {
        unsigned o = __shfl_down_sync(0xFFFFFFFFu, v, off);
        if (lane + off < 32) v += o;
    }
    if (lane == 0) s_wsum[wid] = v;

    int pc = poscnt;
    #pragma unroll
    for (int off = 16; off; off >>= 1) pc += __shfl_down_sync(0xFFFFFFFFu, pc, off);
    if (lane == 0) s_posr[wid] = pc;
    __syncthreads();

    int post = 0;
    #pragma unroll
    for (int w = 0; w < NW; w++) post += s_posr[w];
    int k0 = 3 * post;
    if (k0 > NC - post) k0 = NC - post;

    unsigned above = v - S;  // bins above mine within my warp
    #pragma unroll
    for (int w = wid + 1; w < NW; w++) above += s_wsum[w];

    if (k0 > 0) {
        unsigned kk = (unsigned)k0;
        if (above < kk && kk <= above + S) {
            unsigned a = above;
            #pragma unroll
            for (int j = 7; j >= 0; j--) {   // walk my 8 bins from the top
                unsigned wv = w4[j >> 1];
                unsigned c  = (j & 1) ? (wv >> 16) : (wv & 0xFFFFu);
                if (kk <= a + c) { s_binv = (unsigned)(tid * 8 + j); s_kkv = kk - a; break; }
                a += c;
            }
        }
    }
    __syncthreads();

    // ---- pass B (from registers): above-bin softplus + gather threshold-bin ----
    float acc = accP;
    if (k0 > 0) {
        const unsigned bsel = s_binv;
        #define G(kc)                                                          \
            do {                                                               \
                unsigned _b = (kc) >> 20;                                      \
                if (_b > bsel) acc += sp(kinv(kc));                            \
                else if (_b == bsel && (kc) != 0u) {                           \
                    int s = atomicAdd(&s_cnt, 1);                              \
                    if (s < CAP) s_cand[s] = (kc);                             \
                }                                                              \
            } while (0)
        #pragma unroll
        for (int j = 0; j < NV; j++) {
            uint4 kv = kreg[j];
            G(kv.x); G(kv.y); G(kv.z); G(kv.w);
        }
        #undef G
    }
    __syncthreads();

    // ---- exact k-th largest among candidates (rank counting) ----
    if (k0 > 0) {
        int M = s_cnt; if (M > CAP) M = CAP;
        const unsigned kk = s_kkv;
        for (int c = tid; c < M; c += NT) {
            unsigned key = s_cand[c];
            unsigned gt = 0, eq = 0;
            for (int j = 0; j < M; j++) {
                unsigned o = s_cand[j];
                gt += (o > key);
                eq += (o == key);
            }
            if (gt < kk && kk <= gt + eq) { s_tkey = key; s_krem = kk - gt; }
        }
    }
    __syncthreads();

    // ---- in-bin selected candidates ----
    if (k0 > 0) {
        const unsigned tk = s_tkey;
        int M = s_cnt; if (M > CAP) M = CAP;
        for (int c = tid; c < M; c += NT) {
            unsigned key = s_cand[c];
            if (key > tk) acc += sp(kinv(key));
        }
    }

    // ---- block reduce + global accumulate + last-block finalize ----
    #pragma unroll
    for (int off = 16; off; off >>= 1) acc += __shfl_down_sync(0xFFFFFFFFu, acc, off);
    if (lane == 0) s_accr[wid] = acc;
    __syncthreads();

    if (tid == 0) {
        float totL = 0.f;
        #pragma unroll
        for (int w = 0; w < NW; w++) totL += s_accr[w];
        if (k0 > 0) totL += (float)s_krem * sp(kinv(s_tkey));  // exact tie correction
        atomicAdd(&g_loss, (double)totL);
        atomicAdd(&g_tsum, (double)post);
        __threadfence();
        unsigned done = atomicAdd(&g_done, 1u);
        if (done == gridDim.x - 1) {
            double L = atomicAdd(&g_loss, 0.0);   // forced memory reads
            double T = atomicAdd(&g_tsum, 0.0);
            out[0] = (float)(L / T);
            // reset for next graph replay (deterministic)
            atomicExch((unsigned long long*)&g_loss, 0ull);
            atomicExch((unsigned long long*)&g_tsum, 0ull);
            __threadfence();
            atomicExch(&g_done, 0u);
        }
    }
}

extern "C" void kernel_launch(void* const* d_in, const int* in_sizes, int n_in,
                              void* d_out, int out_size) {
    const float* pred   = (const float*)d_in[0];
    const float* target = (const float*)d_in[1];
    float* out = (float*)d_out;
    int rows = in_sizes[0] / NC;

    hardneg<<<rows, NT>>>(pred, target, out);
}

// round 8
// speedup vs baseline: 1.0620x; 1.0620x over previous
#include <cuda_runtime.h>

// N=8192 rows, C=5000 classes, RATIO=3
#define NC    5000
#define NT    256
#define NW    8
#define NV    5      // ceil(1250 float4 / 256 threads)
#define NV4   1250   // float4 count per row
#define HW    2048   // histogram words: 4096 bins, two 16-bit counts per word
#define CAP   1024   // threshold-bin candidate capacity

// pivot keys (order-preserving transform of 1.0f, 1.5f, 2.0f)
#define PK1   0xBF800000u
#define PK2   0xBFC00000u
#define PK3   0xC0000000u

__device__ double   g_loss = 0.0;
__device__ double   g_tsum = 0.0;
__device__ unsigned g_done = 0;

__device__ __forceinline__ unsigned fkey(float f) {
    unsigned b = __float_as_uint(f);
    return (b & 0x80000000u) ? ~b : (b | 0x80000000u);
}
__device__ __forceinline__ float kinv(unsigned k) {
    return __uint_as_float((k & 0x80000000u) ? (k & 0x7FFFFFFFu) : ~k);
}
__device__ __forceinline__ float sp(float x) {
    float l = __logf(1.f + __expf(-fabsf(x)));
    return x > 0.f ? x + l : l;
}

__global__ void __launch_bounds__(NT, 5)
hardneg(const float* __restrict__ pred, const float* __restrict__ target,
        float* __restrict__ out)
{
    __shared__ unsigned s_hist[HW];    // 8192 B : packed 16-bit counts (4096 bins)
    __shared__ unsigned s_cand[CAP];   // 4096 B
    __shared__ unsigned s_wsum[NW];
    __shared__ unsigned s_cnt2[NW * 2];
    __shared__ float    s_accr[NW];
    __shared__ unsigned s_binv, s_kkv, s_tkey, s_krem;
    __shared__ int      s_cnt;

    const int tid  = threadIdx.x;
    const int lane = tid & 31;
    const int wid  = tid >> 5;
    const int row  = blockIdx.x;

    const float4* p4 = (const float4*)(pred   + (size_t)row * NC);
    const float4* t4 = (const float4*)(target + (size_t)row * NC);

    // zero histogram (2 uint4 per thread)
    ((uint4*)s_hist)[tid]      = make_uint4(0, 0, 0, 0);
    ((uint4*)s_hist)[tid + NT] = make_uint4(0, 0, 0, 0);
    if (tid == 0) s_cnt = 0;
    __syncthreads();

    // ---- pass A: load, key->registers, positive BCE, pivot counts (ALU only) ----
    int   poscnt = 0;
    float accP   = 0.f;
    int   c1 = 0, c2 = 0, c3 = 0;
    uint4 kreg[NV];

    #define PROC(px, tx, kout)                                             \
        do {                                                               \
            float _x = (px);                                               \
            if ((tx) != 0.f) {                                             \
                poscnt++; accP += sp(_x) - _x; (kout) = 0u;                \
            } else {                                                       \
                unsigned _k = fkey(_x); (kout) = _k;                       \
                c1 += (_k > PK1); c2 += (_k > PK2); c3 += (_k > PK3);      \
            }                                                              \
        } while (0)

    #pragma unroll
    for (int j = 0; j < NV; j++) {
        int i = j * NT + tid;
        uint4 k = make_uint4(0, 0, 0, 0);
        if (j < NV - 1 || i < NV4) {
            float4 p = p4[i];
            float4 t = t4[i];
            PROC(p.x, t.x, k.x);
            PROC(p.y, t.y, k.y);
            PROC(p.z, t.z, k.z);
            PROC(p.w, t.w, k.w);
        }
        kreg[j] = k;
    }
    #undef PROC

    // ---- block-reduce packed counts: (c1|c2<<16), (c3|pos<<16) ----
    unsigned pA = (unsigned)c1 | ((unsigned)c2 << 16);
    unsigned pB = (unsigned)c3 | ((unsigned)poscnt << 16);
    #pragma unroll
    for (int off = 16; off; off >>= 1) {
        pA += __shfl_down_sync(0xFFFFFFFFu, pA, off);
        pB += __shfl_down_sync(0xFFFFFFFFu, pB, off);
    }
    if (lane == 0) { s_cnt2[wid * 2] = pA; s_cnt2[wid * 2 + 1] = pB; }
    __syncthreads();

    unsigned tA = 0, tB = 0;
    #pragma unroll
    for (int w = 0; w < NW; w++) { tA += s_cnt2[w * 2]; tB += s_cnt2[w * 2 + 1]; }
    const unsigned C1 = tA & 0xFFFFu, C2 = tA >> 16, C3 = tB & 0xFFFFu;
    const int post = (int)(tB >> 16);

    int k0 = 3 * post;
    if (k0 > NC - post) k0 = NC - post;
    const unsigned kk = (unsigned)k0;

    // largest pivot with count >= k0 (fallback 0 = histogram all negatives)
    const unsigned pivot = (C3 >= kk) ? PK3 : (C2 >= kk) ? PK2 : (C1 >= kk) ? PK1 : 0u;

    // ---- gated histogram: only elements above pivot (~330 atomics/CTA) ----
    if (k0 > 0) {
        #define H(kc)                                                       \
            if ((kc) > pivot)                                               \
                atomicAdd(&s_hist[(kc) >> 21],                              \
                          (((kc) >> 20) & 1u) ? 65536u : 1u);
        #pragma unroll
        for (int j = 0; j < NV; j++) {
            uint4 kv = kreg[j];
            H(kv.x) H(kv.y) H(kv.z) H(kv.w)
        }
        #undef H
    }
    __syncthreads();

    // ---- locate threshold bin: suffix counts via shuffle scan ----
    unsigned w8[8];
    unsigned S = 0;
    #pragma unroll
    for (int j = 0; j < 8; j++) {
        unsigned v = s_hist[tid * 8 + j];
        w8[j] = v;
        S += (v & 0xFFFFu) + (v >> 16);
    }
    unsigned v = S;
    #pragma unroll
    for (int off = 1; off < 32; off <<= 1) {
        unsigned o = __shfl_down_sync(0xFFFFFFFFu, v, off);
        if (lane + off < 32) v += o;
    }
    if (lane == 0) s_wsum[wid] = v;
    __syncthreads();

    unsigned above = v - S;
    #pragma unroll
    for (int w = wid + 1; w < NW; w++) above += s_wsum[w];

    if (k0 > 0) {
        if (above < kk && kk <= above + S) {
            unsigned a = above;
            #pragma unroll
            for (int j = 15; j >= 0; j--) {
                unsigned wv = w8[j >> 1];
                unsigned c  = (j & 1) ? (wv >> 16) : (wv & 0xFFFFu);
                if (kk <= a + c) { s_binv = (unsigned)(tid * 16 + j); s_kkv = kk - a; break; }
                a += c;
            }
        }
    }
    __syncthreads();

    // ---- pass B (registers): above-bin softplus + gather threshold-bin (>pivot) ----
    float acc = accP;
    if (k0 > 0) {
        const unsigned bsel = s_binv;
        #define G(kc)                                                          \
            do {                                                               \
                unsigned _b = (kc) >> 20;                                      \
                if (_b > bsel) acc += sp(kinv(kc));                            \
                else if (_b == bsel && (kc) > pivot) {                         \
                    int s = atomicAdd(&s_cnt, 1);                              \
                    if (s < CAP) s_cand[s] = (kc);                             \
                }                                                              \
            } while (0)
        #pragma unroll
        for (int j = 0; j < NV; j++) {
            uint4 kv = kreg[j];
            G(kv.x); G(kv.y); G(kv.z); G(kv.w);
        }
        #undef G
    }
    __syncthreads();

    // ---- exact k-th largest among candidates (rank counting) ----
    if (k0 > 0) {
        int M = s_cnt; if (M > CAP) M = CAP;
        const unsigned kk2 = s_kkv;
        for (int c = tid; c < M; c += NT) {
            unsigned key = s_cand[c];
            unsigned gt = 0, eq = 0;
            for (int j = 0; j < M; j++) {
                unsigned o = s_cand[j];
                gt += (o > key);
                eq += (o == key);
            }
            if (gt < kk2 && kk2 <= gt + eq) { s_tkey = key; s_krem = kk2 - gt; }
        }
    }
    __syncthreads();

    // ---- in-bin selected candidates ----
    if (k0 > 0) {
        const unsigned tk = s_tkey;
        int M = s_cnt; if (M > CAP) M = CAP;
        for (int c = tid; c < M; c += NT) {
            unsigned key = s_cand[c];
            if (key > tk) acc += sp(kinv(key));
        }
    }

    // ---- block reduce + global accumulate + last-block finalize ----
    #pragma unroll
    for (int off = 16; off; off >>= 1) acc += __shfl_down_sync(0xFFFFFFFFu, acc, off);
    if (lane == 0) s_accr[wid] = acc;
    __syncthreads();

    if (tid == 0) {
        float totL = 0.f;
        #pragma unroll
        for (int w = 0; w < NW; w++) totL += s_accr[w];
        if (k0 > 0) totL += (float)s_krem * sp(kinv(s_tkey));
        atomicAdd(&g_loss, (double)totL);
        atomicAdd(&g_tsum, (double)post);
        __threadfence();
        unsigned done = atomicAdd(&g_done, 1u);
        if (done == gridDim.x - 1) {
            double L = atomicAdd(&g_loss, 0.0);
            double T = atomicAdd(&g_tsum, 0.0);
            out[0] = (float)(L / T);
            atomicExch((unsigned long long*)&g_loss, 0ull);
            atomicExch((unsigned long long*)&g_tsum, 0ull);
            __threadfence();
            atomicExch(&g_done, 0u);
        }
    }
}

extern "C" void kernel_launch(void* const* d_in, const int* in_sizes, int n_in,
                              void* d_out, int out_size) {
    const float* pred   = (const float*)d_in[0];
    const float* target = (const float*)d_in[1];
    float* out = (float*)d_out;
    int rows = in_sizes[0] / NC;

    hardneg<<<rows, NT>>>(pred, target, out);
}

// round 9
// speedup vs baseline: 1.6182x; 1.5237x over previous
#include <cuda_runtime.h>

// N=8192 rows, C=5000 classes, RATIO=3
#define NC    5000
#define NT    256
#define NW    8
#define NV4   1250          // float4 per row
#define CAP   768           // list / candidate capacity
#define NBF   2048          // fast-path fine bins (8KB)
#define PK    0xBFC00000u   // fkey(1.5f): pivot key

__device__ double   g_loss = 0.0;
__device__ double   g_tsum = 0.0;
__device__ unsigned g_done = 0;

__device__ __forceinline__ unsigned fkey(float f) {
    unsigned b = __float_as_uint(f);
    return (b & 0x80000000u) ? ~b : (b | 0x80000000u);
}
__device__ __forceinline__ float kinv(unsigned k) {
    return __uint_as_float((k & 0x80000000u) ? (k & 0x7FFFFFFFu) : ~k);
}
__device__ __forceinline__ float sp(float x) {
    float l = __logf(1.f + __expf(-fabsf(x)));
    return x > 0.f ? x + l : l;
}
__device__ __forceinline__ unsigned fbin(unsigned key) {   // fast-path bin, monotone
    unsigned b = (key - PK) >> 17;
    return b > (NBF - 1) ? (NBF - 1) : b;
}

__global__ void __launch_bounds__(NT)
hardneg(const float* __restrict__ pred, const float* __restrict__ target,
        float* __restrict__ out)
{
    __shared__ unsigned s_hist[NBF];   // 8KB (fast: plain counts; fallback: packed 4096)
    __shared__ unsigned s_list[CAP];   // 3KB
    __shared__ unsigned s_cand[CAP];   // 3KB
    __shared__ unsigned s_wsum[NW];
    __shared__ int      s_posr[NW];
    __shared__ float    s_accr[NW];
    __shared__ unsigned s_binv, s_kkv, s_tkey, s_krem;
    __shared__ int      s_cnt, s_ccnt;

    const int tid  = threadIdx.x;
    const int lane = tid & 31;
    const int wid  = tid >> 5;
    const int row  = blockIdx.x;

    const float*  prow = pred   + (size_t)row * NC;
    const float*  trow = target + (size_t)row * NC;
    const float4* p4 = (const float4*)prow;
    const float4* t4 = (const float4*)trow;

    ((uint4*)s_hist)[tid]      = make_uint4(0, 0, 0, 0);
    ((uint4*)s_hist)[tid + NT] = make_uint4(0, 0, 0, 0);
    if (tid == 0) { s_cnt = 0; s_ccnt = 0; }
    __syncthreads();

    // ======== hot pass: load + rare positive BCE + push keys > pivot ========
    int   poscnt = 0;
    float accP   = 0.f;

    #define PROC(px, tx)                                                    \
        do {                                                                \
            float _x = (px);                                                \
            unsigned _k = fkey(_x);                                         \
            if ((tx) != 0.f) {                                              \
                poscnt++; accP += sp(_x) - _x;                              \
            } else if (_k > PK) {                                           \
                int _s = atomicAdd(&s_cnt, 1);                              \
                if (_s < CAP) s_list[_s] = _k;                              \
            }                                                               \
        } while (0)

    #pragma unroll
    for (int j = 0; j < 5; j++) {
        int i = j * NT + tid;
        if (j < 4 || i < NV4) {
            float4 p = p4[i];
            float4 t = t4[i];
            PROC(p.x, t.x);
            PROC(p.y, t.y);
            PROC(p.z, t.z);
            PROC(p.w, t.w);
        }
    }
    #undef PROC

    int pc = poscnt;
    #pragma unroll
    for (int off = 16; off; off >>= 1) pc += __shfl_down_sync(0xFFFFFFFFu, pc, off);
    if (lane == 0) s_posr[wid] = pc;
    __syncthreads();

    int post = 0;
    #pragma unroll
    for (int w = 0; w < NW; w++) post += s_posr[w];
    int k0 = 3 * post;
    if (k0 > NC - post) k0 = NC - post;
    const unsigned kk = (unsigned)k0;

    const int  cnt  = s_cnt;
    const bool fast = (cnt >= k0) && (cnt <= CAP);
    float acc = accP;

    if (k0 > 0 && fast) {
        // ---- histogram of the list (fine offset bins) ----
        for (int i = tid; i < cnt; i += NT)
            atomicAdd(&s_hist[fbin(s_list[i])], 1u);
        __syncthreads();

        // ---- suffix scan: thread owns 8 bins ----
        unsigned w8[8];
        unsigned S = 0;
        #pragma unroll
        for (int j = 0; j < 8; j++) { w8[j] = s_hist[tid * 8 + j]; S += w8[j]; }
        unsigned v = S;
        #pragma unroll
        for (int off = 1; off < 32; off <<= 1) {
            unsigned o = __shfl_down_sync(0xFFFFFFFFu, v, off);
            if (lane + off < 32) v += o;
        }
        if (lane == 0) s_wsum[wid] = v;
        __syncthreads();

        unsigned above = v - S;
        #pragma unroll
        for (int w = wid + 1; w < NW; w++) above += s_wsum[w];
        if (above < kk && kk <= above + S) {
            unsigned a = above;
            #pragma unroll
            for (int j = 7; j >= 0; j--) {
                unsigned c = w8[j];
                if (kk <= a + c) { s_binv = (unsigned)(tid * 8 + j); s_kkv = kk - a; break; }
                a += c;
            }
        }
        __syncthreads();

        // ---- list scan: above-bin softplus + gather threshold-bin candidates ----
        const unsigned bv = s_binv;
        for (int i = tid; i < cnt; i += NT) {
            unsigned key = s_list[i];
            unsigned b   = fbin(key);
            if (b > bv) acc += sp(kinv(key));
            else if (b == bv) {
                int s = atomicAdd(&s_ccnt, 1);
                if (s < CAP) s_cand[s] = key;
            }
        }
    } else if (k0 > 0) {
        // ======== cold exact fallback (R4 algorithm, global re-reads) ========
        ((uint4*)s_hist)[tid]      = make_uint4(0, 0, 0, 0);
        ((uint4*)s_hist)[tid + NT] = make_uint4(0, 0, 0, 0);
        __syncthreads();
        for (int i = tid; i < NC; i += NT) {
            if (trow[i] == 0.f) {
                unsigned k = fkey(prow[i]);
                atomicAdd(&s_hist[k >> 21], ((k >> 20) & 1u) ? 65536u : 1u);
            }
        }
        __syncthreads();

        unsigned w8[8];
        unsigned S = 0;
        #pragma unroll
        for (int j = 0; j < 8; j++) {
            unsigned vv = s_hist[tid * 8 + j];
            w8[j] = vv;
            S += (vv & 0xFFFFu) + (vv >> 16);
        }
        unsigned v = S;
        #pragma unroll
        for (int off = 1; off < 32; off <<= 1) {
            unsigned o = __shfl_down_sync(0xFFFFFFFFu, v, off);
            if (lane + off < 32) v += o;
        }
        if (lane == 0) s_wsum[wid] = v;
        __syncthreads();

        unsigned above = v - S;
        #pragma unroll
        for (int w = wid + 1; w < NW; w++) above += s_wsum[w];
        if (above < kk && kk <= above + S) {
            unsigned a = above;
            #pragma unroll
            for (int j = 15; j >= 0; j--) {
                unsigned wv = w8[j >> 1];
                unsigned c  = (j & 1) ? (wv >> 16) : (wv & 0xFFFFu);
                if (kk <= a + c) { s_binv = (unsigned)(tid * 16 + j); s_kkv = kk - a; break; }
                a += c;
            }
        }
        __syncthreads();

        const unsigned bv = s_binv;
        for (int i = tid; i < NC; i += NT) {
            if (trow[i] == 0.f) {
                unsigned k = fkey(prow[i]);
                unsigned b = k >> 20;
                if (b > bv) acc += sp(kinv(k));
                else if (b == bv) {
                    int s = atomicAdd(&s_ccnt, 1);
                    if (s < CAP) s_cand[s] = k;
                }
            }
        }
    }
    __syncthreads();

    // ======== exact k-th largest among candidates (rank counting) ========
    if (k0 > 0) {
        int M = s_ccnt; if (M > CAP) M = CAP;
        const unsigned kk2 = s_kkv;
        for (int c = tid; c < M; c += NT) {
            unsigned key = s_cand[c];
            unsigned gt = 0, eq = 0;
            for (int j = 0; j < M; j++) {
                unsigned o = s_cand[j];
                gt += (o > key);
                eq += (o == key);
            }
            if (gt < kk2 && kk2 <= gt + eq) { s_tkey = key; s_krem = kk2 - gt; }
        }
    }
    __syncthreads();

    if (k0 > 0) {
        const unsigned tk = s_tkey;
        int M = s_ccnt; if (M > CAP) M = CAP;
        for (int c = tid; c < M; c += NT) {
            unsigned key = s_cand[c];
            if (key > tk) acc += sp(kinv(key));
        }
    }

    // ======== block reduce + global accumulate + last-block finalize ========
    #pragma unroll
    for (int off = 16; off; off >>= 1) acc += __shfl_down_sync(0xFFFFFFFFu, acc, off);
    if (lane == 0) s_accr[wid] = acc;
    __syncthreads();

    if (tid == 0) {
        float totL = 0.f;
        #pragma unroll
        for (int w = 0; w < NW; w++) totL += s_accr[w];
        if (k0 > 0) totL += (float)s_krem * sp(kinv(s_tkey));  // exact tie correction
        atomicAdd(&g_loss, (double)totL);
        atomicAdd(&g_tsum, (double)post);
        __threadfence();
        unsigned done = atomicAdd(&g_done, 1u);
        if (done == gridDim.x - 1) {
            double L = atomicAdd(&g_loss, 0.0);
            double T = atomicAdd(&g_tsum, 0.0);
            out[0] = (float)(L / T);
            atomicExch((unsigned long long*)&g_loss, 0ull);
            atomicExch((unsigned long long*)&g_tsum, 0ull);
            __threadfence();
            atomicExch(&g_done, 0u);
        }
    }
}

extern "C" void kernel_launch(void* const* d_in, const int* in_sizes, int n_in,
                              void* d_out, int out_size) {
    const float* pred   = (const float*)d_in[0];
    const float* target = (const float*)d_in[1];
    float* out = (float*)d_out;
    int rows = in_sizes[0] / NC;

    hardneg<<<rows, NT>>>(pred, target, out);
}